// round 2
// baseline (speedup 1.0000x reference)
#include <cuda_runtime.h>
#include <math.h>
#include <stdint.h>

#define N_NODES 12288
#define D_IN    512
#define HID     256
#define D_OUT   64
#define E_EDGES 393216

// ---------------- scratch (device globals: no runtime allocation) ----------
__device__ float  g_h0[(size_t)N_NODES * HID];   // 12.6 MB
__device__ float  g_h1[(size_t)N_NODES * HID];   // 12.6 MB
__device__ float  g_z [(size_t)N_NODES * D_OUT]; // 3.1 MB
__device__ float  g_zn[(size_t)N_NODES * D_OUT]; // 3.1 MB (row-normalized)
__device__ double g_loss_sum;

// ---------------------------------------------------------------------------
// Generic tiled fp32 GEMM:  C = act(A[M,K] @ B[K,N] + bias)
// ---------------------------------------------------------------------------
template<int BM, int BN, int BK, int TM, int TN, bool RELU>
__global__ __launch_bounds__((BM/TM)*(BN/TN))
void gemm_bias_kernel(const float* __restrict__ A,
                      const float* __restrict__ B,
                      const float* __restrict__ bias,
                      float* __restrict__ C,
                      int M, int Nn, int K)
{
    __shared__ float As[BK][BM];   // A tile stored transposed (k-major)
    __shared__ float Bs[BK][BN];

    constexpr int THREADS = (BM/TM)*(BN/TN);
    const int tid = threadIdx.x;
    const int tx  = tid % (BN/TN);
    const int ty  = tid / (BN/TN);
    const int rowBase = blockIdx.y * BM;
    const int colBase = blockIdx.x * BN;

    float acc[TM][TN];
#pragma unroll
    for (int i = 0; i < TM; i++)
#pragma unroll
        for (int j = 0; j < TN; j++) acc[i][j] = 0.f;

    for (int kk = 0; kk < K; kk += BK) {
        // load A tile (BM x BK) -> As[k][m]
        constexpr int AV = BM * BK / 4;
#pragma unroll
        for (int v = tid; v < AV; v += THREADS) {
            int row = v / (BK/4);
            int kv  = v % (BK/4);
            float4 t = *reinterpret_cast<const float4*>(
                &A[(size_t)(rowBase + row) * K + kk + kv*4]);
            As[kv*4+0][row] = t.x; As[kv*4+1][row] = t.y;
            As[kv*4+2][row] = t.z; As[kv*4+3][row] = t.w;
        }
        // load B tile (BK x BN) -> Bs[k][n]
        constexpr int BV = BK * BN / 4;
#pragma unroll
        for (int v = tid; v < BV; v += THREADS) {
            int kr = v / (BN/4);
            int nv = v % (BN/4);
            *reinterpret_cast<float4*>(&Bs[kr][nv*4]) =
                *reinterpret_cast<const float4*>(
                    &B[(size_t)(kk + kr) * Nn + colBase + nv*4]);
        }
        __syncthreads();

#pragma unroll
        for (int k = 0; k < BK; k++) {
            float a[TM], b[TN];
#pragma unroll
            for (int i = 0; i < TM; i += 4)
                *reinterpret_cast<float4*>(&a[i]) =
                    *reinterpret_cast<const float4*>(&As[k][ty*TM + i]);
#pragma unroll
            for (int j = 0; j < TN; j += 4)
                *reinterpret_cast<float4*>(&b[j]) =
                    *reinterpret_cast<const float4*>(&Bs[k][tx*TN + j]);
#pragma unroll
            for (int i = 0; i < TM; i++)
#pragma unroll
                for (int j = 0; j < TN; j++)
                    acc[i][j] += a[i] * b[j];
        }
        __syncthreads();
    }

    // epilogue: bias + optional ReLU, float4 stores
#pragma unroll
    for (int i = 0; i < TM; i++) {
        const size_t row = rowBase + ty*TM + i;
#pragma unroll
        for (int jv = 0; jv < TN/4; jv++) {
            const int col = colBase + tx*TN + jv*4;
            float4 o;
            o.x = acc[i][jv*4+0] + bias[col+0];
            o.y = acc[i][jv*4+1] + bias[col+1];
            o.z = acc[i][jv*4+2] + bias[col+2];
            o.w = acc[i][jv*4+3] + bias[col+3];
            if (RELU) {
                o.x = fmaxf(o.x, 0.f); o.y = fmaxf(o.y, 0.f);
                o.z = fmaxf(o.z, 0.f); o.w = fmaxf(o.w, 0.f);
            }
            *reinterpret_cast<float4*>(&C[row * Nn + col]) = o;
        }
    }
}

// ---------------------------------------------------------------------------
// Row-normalize z -> zn  (one warp per row, D_OUT = 64)
// ---------------------------------------------------------------------------
__global__ __launch_bounds__(256)
void normalize_kernel(const float* __restrict__ Z, float* __restrict__ Zn)
{
    const int lane = threadIdx.x & 31;
    const int warp = threadIdx.x >> 5;
    const int row  = blockIdx.x * 8 + warp;
    float2 a = *reinterpret_cast<const float2*>(&Z[(size_t)row * D_OUT + lane*2]);
    float ss = a.x*a.x + a.y*a.y;
#pragma unroll
    for (int o = 16; o > 0; o >>= 1) ss += __shfl_xor_sync(0xffffffffu, ss, o);
    float inv = rsqrtf(fmaxf(ss, 1e-30f));
    float2 r = make_float2(a.x * inv, a.y * inv);
    *reinterpret_cast<float2*>(&Zn[(size_t)row * D_OUT + lane*2]) = r;
}

// ---------------------------------------------------------------------------
// Edge reconstruction loss: sum over edges of softplus(-cos(src,dst))
// One warp per edge, grid-strided; block-reduced; one double atomic per block.
// edge_index arrives as int32 (JAX default integer width).
// ---------------------------------------------------------------------------
__global__ __launch_bounds__(256)
void edge_loss_kernel(const int* __restrict__ ei,
                      const float* __restrict__ Zn)
{
    const int lane = threadIdx.x & 31;
    const int warp = threadIdx.x >> 5;
    const int gw   = blockIdx.x * 8 + warp;
    const int nw   = gridDim.x * 8;
    float lsum = 0.f;
    for (int e = gw; e < E_EDGES; e += nw) {
        const int s = ei[e];
        const int d = ei[E_EDGES + e];
        float2 a = *reinterpret_cast<const float2*>(&Zn[(size_t)s * D_OUT + lane*2]);
        float2 b = *reinterpret_cast<const float2*>(&Zn[(size_t)d * D_OUT + lane*2]);
        float p = a.x*b.x + a.y*b.y;
#pragma unroll
        for (int o = 16; o > 0; o >>= 1) p += __shfl_xor_sync(0xffffffffu, p, o);
        if (lane == 0) lsum += log1pf(__expf(-p));   // -log(sigmoid(p))
    }
    __shared__ float wsum[8];
    if (lane == 0) wsum[warp] = lsum;
    __syncthreads();
    if (threadIdx.x == 0) {
        float t = 0.f;
#pragma unroll
        for (int i = 0; i < 8; i++) t += wsum[i];
        atomicAdd(&g_loss_sum, (double)t);
    }
}

__global__ void zero_loss_kernel() { g_loss_sum = 0.0; }

__global__ void write_loss_kernel(float* __restrict__ out)
{
    out[(size_t)N_NODES * N_NODES] = (float)(g_loss_sum / (double)E_EDGES);
}

// ---------------------------------------------------------------------------
// Symmetric gram + sigmoid:  Out = sigmoid(Zn @ Zn^T)   (K = 64)
// Computes upper-triangular blocks only; mirrors off-diagonal tiles through a
// shared-memory transpose stage so both writes stay coalesced.
// ---------------------------------------------------------------------------
__global__ __launch_bounds__(256)
void gram_sigmoid_kernel(const float* __restrict__ Z, float* __restrict__ Out)
{
    constexpr int BM = 128, BN = 128, BK = 32, TM = 8, TN = 8;
    constexpr int TSTRIDE = 132;              // staging row stride (16B aligned)
    __shared__ float smem[2 * BK * BM];       // 32 KB: As | Bs, reused for stage
    float* As = smem;                         // As[k*BM + m]
    float* Bs = smem + BK * BM;               // Bs[k*BM + n]

    const int bi = blockIdx.y;                // row block
    const int bj = blockIdx.x;                // col block
    if (bj < bi) return;                      // upper triangle only

    const int tid = threadIdx.x;
    const int tx  = tid & 15;
    const int ty  = tid >> 4;
    const int rowBase = bi * BM;
    const int colBase = bj * BN;

    float acc[TM][TN];
#pragma unroll
    for (int i = 0; i < TM; i++)
#pragma unroll
        for (int j = 0; j < TN; j++) acc[i][j] = 0.f;

    for (int kk = 0; kk < D_OUT; kk += BK) {
#pragma unroll
        for (int v = tid; v < BM * BK / 4; v += 256) {
            int row = v >> 3;      // / (BK/4)
            int kv  = v & 7;
            float4 a = *reinterpret_cast<const float4*>(
                &Z[(size_t)(rowBase + row) * D_OUT + kk + kv*4]);
            As[(kv*4+0)*BM + row] = a.x; As[(kv*4+1)*BM + row] = a.y;
            As[(kv*4+2)*BM + row] = a.z; As[(kv*4+3)*BM + row] = a.w;
            float4 b = *reinterpret_cast<const float4*>(
                &Z[(size_t)(colBase + row) * D_OUT + kk + kv*4]);
            Bs[(kv*4+0)*BM + row] = b.x; Bs[(kv*4+1)*BM + row] = b.y;
            Bs[(kv*4+2)*BM + row] = b.z; Bs[(kv*4+3)*BM + row] = b.w;
        }
        __syncthreads();

#pragma unroll
        for (int k = 0; k < BK; k++) {
            float a[TM], b[TN];
            *reinterpret_cast<float4*>(&a[0]) =
                *reinterpret_cast<const float4*>(&As[k*BM + ty*TM]);
            *reinterpret_cast<float4*>(&a[4]) =
                *reinterpret_cast<const float4*>(&As[k*BM + ty*TM + 4]);
            *reinterpret_cast<float4*>(&b[0]) =
                *reinterpret_cast<const float4*>(&Bs[k*BM + tx*TN]);
            *reinterpret_cast<float4*>(&b[4]) =
                *reinterpret_cast<const float4*>(&Bs[k*BM + tx*TN + 4]);
#pragma unroll
            for (int i = 0; i < TM; i++)
#pragma unroll
                for (int j = 0; j < TN; j++)
                    acc[i][j] += a[i] * b[j];
        }
        __syncthreads();
    }

    // sigmoid in place
#pragma unroll
    for (int i = 0; i < TM; i++)
#pragma unroll
        for (int j = 0; j < TN; j++)
            acc[i][j] = 1.f / (1.f + __expf(-acc[i][j]));

    // direct (upper) tile write, coalesced float4
#pragma unroll
    for (int i = 0; i < TM; i++) {
        const size_t row = rowBase + ty*TM + i;
#pragma unroll
        for (int jv = 0; jv < TN/4; jv++) {
            const int col = colBase + tx*TN + jv*4;
            float4 o = make_float4(acc[i][jv*4+0], acc[i][jv*4+1],
                                   acc[i][jv*4+2], acc[i][jv*4+3]);
            *reinterpret_cast<float4*>(&Out[row * N_NODES + col]) = o;
        }
    }

    // mirrored (lower) tile via shared-memory transpose stage
    if (bj > bi) {
        for (int c0 = 0; c0 < BN; c0 += 32) {
            __syncthreads();
            if (tx*TN >= c0 && tx*TN < c0 + 32) {
                const int base_c = tx*TN - c0;
#pragma unroll
                for (int j = 0; j < TN; j++)
#pragma unroll
                    for (int i = 0; i < TM; i++)
                        smem[(base_c + j)*TSTRIDE + ty*TM + i] = acc[i][j];
            }
            __syncthreads();
#pragma unroll
            for (int v = tid; v < 32 * (BM/4); v += 256) {
                const int cl = v >> 5;       // / (BM/4)
                const int nv = v & 31;
                float4 t = *reinterpret_cast<const float4*>(
                    &smem[cl*TSTRIDE + nv*4]);
                *reinterpret_cast<float4*>(
                    &Out[(size_t)(colBase + c0 + cl) * N_NODES + rowBase + nv*4]) = t;
            }
        }
    }
}

// ---------------------------------------------------------------------------
extern "C" void kernel_launch(void* const* d_in, const int* in_sizes, int n_in,
                              void* d_out, int out_size)
{
    const float* x  = (const float*)d_in[0];
    const int*   ei = (const int*)  d_in[1];
    const float* W0 = (const float*)d_in[2];
    const float* b0 = (const float*)d_in[3];
    const float* W1 = (const float*)d_in[4];
    const float* b1 = (const float*)d_in[5];
    const float* W2 = (const float*)d_in[6];
    const float* b2 = (const float*)d_in[7];
    float* out = (float*)d_out;

    void *p_h0, *p_h1, *p_z, *p_zn;
    cudaGetSymbolAddress(&p_h0, g_h0);
    cudaGetSymbolAddress(&p_h1, g_h1);
    cudaGetSymbolAddress(&p_z,  g_z);
    cudaGetSymbolAddress(&p_zn, g_zn);
    float* h0 = (float*)p_h0;
    float* h1 = (float*)p_h1;
    float* z  = (float*)p_z;
    float* zn = (float*)p_zn;

    zero_loss_kernel<<<1, 1>>>();

    // encoder
    gemm_bias_kernel<128,128,32,8,8,true><<<dim3(HID/128,   N_NODES/128), 256>>>(
        x,  W0, b0, h0, N_NODES, HID,   D_IN);
    gemm_bias_kernel<128,128,32,8,8,true><<<dim3(HID/128,   N_NODES/128), 256>>>(
        h0, W1, b1, h1, N_NODES, HID,   HID);
    gemm_bias_kernel<128, 64,32,8,4,false><<<dim3(D_OUT/64, N_NODES/128), 256>>>(
        h1, W2, b2, z,  N_NODES, D_OUT, HID);

    // normalize rows
    normalize_kernel<<<N_NODES/8, 256>>>(z, zn);

    // edge loss
    edge_loss_kernel<<<1024, 256>>>(ei, zn);

    // full similarity matrix (symmetric)
    gram_sigmoid_kernel<<<dim3(N_NODES/128, N_NODES/128), 256>>>(zn, out);

    // scalar loss at the end of the output buffer
    if ((long long)out_size > (long long)N_NODES * N_NODES)
        write_loss_kernel<<<1, 1>>>(out);
}

// round 3
// speedup vs baseline: 1.4880x; 1.4880x over previous
#include <cuda_runtime.h>
#include <math.h>
#include <stdint.h>

#define N_NODES 12288
#define D_IN    512
#define HID     256
#define D_OUT   64
#define E_EDGES 393216

// ---------------- scratch (device globals: no runtime allocation) ----------
__device__ float  g_h0[(size_t)N_NODES * HID];
__device__ float  g_h1[(size_t)N_NODES * HID];
__device__ float  g_z [(size_t)N_NODES * D_OUT];
__device__ float  g_zn[(size_t)N_NODES * D_OUT];
__device__ double g_loss_sum;

// ---------------------------------------------------------------------------
// Generic tiled fp32 GEMM:  C = act(A[M,K] @ B[K,N] + bias)   (encoder)
// ---------------------------------------------------------------------------
template<int BM, int BN, int BK, int TM, int TN, bool RELU>
__global__ __launch_bounds__((BM/TM)*(BN/TN))
void gemm_bias_kernel(const float* __restrict__ A,
                      const float* __restrict__ B,
                      const float* __restrict__ bias,
                      float* __restrict__ C,
                      int M, int Nn, int K)
{
    __shared__ float As[BK][BM];
    __shared__ float Bs[BK][BN];

    constexpr int THREADS = (BM/TM)*(BN/TN);
    const int tid = threadIdx.x;
    const int tx  = tid % (BN/TN);
    const int ty  = tid / (BN/TN);
    const int rowBase = blockIdx.y * BM;
    const int colBase = blockIdx.x * BN;

    float acc[TM][TN];
#pragma unroll
    for (int i = 0; i < TM; i++)
#pragma unroll
        for (int j = 0; j < TN; j++) acc[i][j] = 0.f;

    for (int kk = 0; kk < K; kk += BK) {
        constexpr int AV = BM * BK / 4;
#pragma unroll
        for (int v = tid; v < AV; v += THREADS) {
            int row = v / (BK/4);
            int kv  = v % (BK/4);
            float4 t = *reinterpret_cast<const float4*>(
                &A[(size_t)(rowBase + row) * K + kk + kv*4]);
            As[kv*4+0][row] = t.x; As[kv*4+1][row] = t.y;
            As[kv*4+2][row] = t.z; As[kv*4+3][row] = t.w;
        }
        constexpr int BV = BK * BN / 4;
#pragma unroll
        for (int v = tid; v < BV; v += THREADS) {
            int kr = v / (BN/4);
            int nv = v % (BN/4);
            *reinterpret_cast<float4*>(&Bs[kr][nv*4]) =
                *reinterpret_cast<const float4*>(
                    &B[(size_t)(kk + kr) * Nn + colBase + nv*4]);
        }
        __syncthreads();

#pragma unroll
        for (int k = 0; k < BK; k++) {
            float a[TM], b[TN];
#pragma unroll
            for (int i = 0; i < TM; i += 4)
                *reinterpret_cast<float4*>(&a[i]) =
                    *reinterpret_cast<const float4*>(&As[k][ty*TM + i]);
#pragma unroll
            for (int j = 0; j < TN; j += 4)
                *reinterpret_cast<float4*>(&b[j]) =
                    *reinterpret_cast<const float4*>(&Bs[k][tx*TN + j]);
#pragma unroll
            for (int i = 0; i < TM; i++)
#pragma unroll
                for (int j = 0; j < TN; j++)
                    acc[i][j] += a[i] * b[j];
        }
        __syncthreads();
    }

#pragma unroll
    for (int i = 0; i < TM; i++) {
        const size_t row = rowBase + ty*TM + i;
#pragma unroll
        for (int jv = 0; jv < TN/4; jv++) {
            const int col = colBase + tx*TN + jv*4;
            float4 o;
            o.x = acc[i][jv*4+0] + bias[col+0];
            o.y = acc[i][jv*4+1] + bias[col+1];
            o.z = acc[i][jv*4+2] + bias[col+2];
            o.w = acc[i][jv*4+3] + bias[col+3];
            if (RELU) {
                o.x = fmaxf(o.x, 0.f); o.y = fmaxf(o.y, 0.f);
                o.z = fmaxf(o.z, 0.f); o.w = fmaxf(o.w, 0.f);
            }
            *reinterpret_cast<float4*>(&C[row * Nn + col]) = o;
        }
    }
}

// ---------------------------------------------------------------------------
// Row-normalize z -> zn  (one warp per row, D_OUT = 64)
// ---------------------------------------------------------------------------
__global__ __launch_bounds__(256)
void normalize_kernel(const float* __restrict__ Z, float* __restrict__ Zn)
{
    const int lane = threadIdx.x & 31;
    const int warp = threadIdx.x >> 5;
    const int row  = blockIdx.x * 8 + warp;
    float2 a = *reinterpret_cast<const float2*>(&Z[(size_t)row * D_OUT + lane*2]);
    float ss = a.x*a.x + a.y*a.y;
#pragma unroll
    for (int o = 16; o > 0; o >>= 1) ss += __shfl_xor_sync(0xffffffffu, ss, o);
    float inv = rsqrtf(fmaxf(ss, 1e-30f));
    float2 r = make_float2(a.x * inv, a.y * inv);
    *reinterpret_cast<float2*>(&Zn[(size_t)row * D_OUT + lane*2]) = r;
}

// ---------------------------------------------------------------------------
// Edge reconstruction loss (edge_index is int32)
// ---------------------------------------------------------------------------
__global__ __launch_bounds__(256)
void edge_loss_kernel(const int* __restrict__ ei,
                      const float* __restrict__ Zn)
{
    const int lane = threadIdx.x & 31;
    const int warp = threadIdx.x >> 5;
    const int gw   = blockIdx.x * 8 + warp;
    const int nw   = gridDim.x * 8;
    float lsum = 0.f;
    for (int e = gw; e < E_EDGES; e += nw) {
        const int s = ei[e];
        const int d = ei[E_EDGES + e];
        float2 a = *reinterpret_cast<const float2*>(&Zn[(size_t)s * D_OUT + lane*2]);
        float2 b = *reinterpret_cast<const float2*>(&Zn[(size_t)d * D_OUT + lane*2]);
        float p = a.x*b.x + a.y*b.y;
#pragma unroll
        for (int o = 16; o > 0; o >>= 1) p += __shfl_xor_sync(0xffffffffu, p, o);
        if (lane == 0) lsum += log1pf(__expf(-p));
    }
    __shared__ float wsum[8];
    if (lane == 0) wsum[warp] = lsum;
    __syncthreads();
    if (threadIdx.x == 0) {
        float t = 0.f;
#pragma unroll
        for (int i = 0; i < 8; i++) t += wsum[i];
        atomicAdd(&g_loss_sum, (double)t);
    }
}

__global__ void zero_loss_kernel() { g_loss_sum = 0.0; }

__global__ void write_loss_kernel(float* __restrict__ out)
{
    out[(size_t)N_NODES * N_NODES] = (float)(g_loss_sum / (double)E_EDGES);
}

// ---------------------------------------------------------------------------
// Gram + sigmoid via tf32 tensor-core mma: Out = sigmoid(Zn @ Zn^T), K=64.
// Upper-triangular blocks only; mirror written via smem-staged transpose.
// ---------------------------------------------------------------------------
__device__ __forceinline__ uint32_t f32_to_tf32(float x) {
    uint32_t r;
    asm("cvt.rna.tf32.f32 %0, %1;" : "=r"(r) : "f"(x));
    return r;
}

__device__ __forceinline__ void mma_tf32(float d[4],
                                         const uint32_t a[4],
                                         const uint32_t b[2]) {
    asm volatile(
        "mma.sync.aligned.m16n8k8.row.col.f32.tf32.tf32.f32 "
        "{%0,%1,%2,%3}, {%4,%5,%6,%7}, {%8,%9}, {%0,%1,%2,%3};"
        : "+f"(d[0]), "+f"(d[1]), "+f"(d[2]), "+f"(d[3])
        : "r"(a[0]), "r"(a[1]), "r"(a[2]), "r"(a[3]),
          "r"(b[0]), "r"(b[1]));
}

#define GRAM_LDK  68     // smem row stride for input tiles (floats)
#define GRAM_LDS  132    // smem row stride for staging tile (floats)
#define GRAM_SMEM_BYTES (2 * 128 * GRAM_LDK * 4)   // 69,632 B (>= stage 67,584)

__global__ __launch_bounds__(256)
void gram_mma_kernel(const float* __restrict__ Z, float* __restrict__ Out)
{
    extern __shared__ float smem[];
    float* As = smem;                       // As[r*GRAM_LDK + k] (tf32 bits)
    float* Bs = smem + 128 * GRAM_LDK;

    const int bi = blockIdx.y;
    const int bj = blockIdx.x;
    if (bj < bi) return;                    // upper triangle only
    const int rowBase = bi * 128;
    const int colBase = bj * 128;

    const int tid  = threadIdx.x;
    const int lane = tid & 31;
    const int wid  = tid >> 5;
    const int wm   = (wid >> 2) * 64;       // warp m-offset: 0 or 64
    const int wn   = (wid & 3) * 32;        // warp n-offset
    const int qr   = lane >> 2;             // 0..7
    const int qc   = lane & 3;              // 0..3

    // ---- load tiles (fp32 -> tf32 once, so A/B sides agree) ----
    for (int v = tid; v < 128 * 16; v += 256) {
        const int r  = v >> 4;
        const int c4 = (v & 15) * 4;
        float4 t = *reinterpret_cast<const float4*>(
            &Z[(size_t)(rowBase + r) * D_OUT + c4]);
        uint32_t* dst = reinterpret_cast<uint32_t*>(&As[r * GRAM_LDK + c4]);
        dst[0] = f32_to_tf32(t.x); dst[1] = f32_to_tf32(t.y);
        dst[2] = f32_to_tf32(t.z); dst[3] = f32_to_tf32(t.w);
    }
    if (bj != bi) {
        for (int v = tid; v < 128 * 16; v += 256) {
            const int r  = v >> 4;
            const int c4 = (v & 15) * 4;
            float4 t = *reinterpret_cast<const float4*>(
                &Z[(size_t)(colBase + r) * D_OUT + c4]);
            uint32_t* dst = reinterpret_cast<uint32_t*>(&Bs[r * GRAM_LDK + c4]);
            dst[0] = f32_to_tf32(t.x); dst[1] = f32_to_tf32(t.y);
            dst[2] = f32_to_tf32(t.z); dst[3] = f32_to_tf32(t.w);
        }
    }
    __syncthreads();

    const float* Bp = (bj == bi) ? As : Bs;

    // ---- mma mainloop: warp computes 64x32 via 4x4 m16n8k8 tiles ----
    float acc[4][4][4];
#pragma unroll
    for (int mt = 0; mt < 4; mt++)
#pragma unroll
        for (int nt = 0; nt < 4; nt++)
#pragma unroll
            for (int i = 0; i < 4; i++) acc[mt][nt][i] = 0.f;

#pragma unroll
    for (int k0 = 0; k0 < D_OUT; k0 += 8) {
        uint32_t a[4][4], b[4][2];
#pragma unroll
        for (int mt = 0; mt < 4; mt++) {
            const uint32_t* base = reinterpret_cast<const uint32_t*>(
                &As[(wm + mt*16 + qr) * GRAM_LDK + k0 + qc]);
            a[mt][0] = base[0];
            a[mt][1] = base[8 * GRAM_LDK];
            a[mt][2] = base[4];
            a[mt][3] = base[8 * GRAM_LDK + 4];
        }
#pragma unroll
        for (int nt = 0; nt < 4; nt++) {
            const uint32_t* base = reinterpret_cast<const uint32_t*>(
                &Bp[(wn + nt*8 + qr) * GRAM_LDK + k0 + qc]);
            b[nt][0] = base[0];
            b[nt][1] = base[4];
        }
#pragma unroll
        for (int mt = 0; mt < 4; mt++)
#pragma unroll
            for (int nt = 0; nt < 4; nt++)
                mma_tf32(acc[mt][nt], a[mt], b[nt]);
    }

    // ---- sigmoid + stage tile into smem (inputs dead after barrier) ----
    __syncthreads();
    float* stg = smem;                      // stg[r*GRAM_LDS + c], 128x128
#pragma unroll
    for (int mt = 0; mt < 4; mt++) {
#pragma unroll
        for (int nt = 0; nt < 4; nt++) {
            float* d = acc[mt][nt];
            float s0 = 1.f / (1.f + __expf(-d[0]));
            float s1 = 1.f / (1.f + __expf(-d[1]));
            float s2 = 1.f / (1.f + __expf(-d[2]));
            float s3 = 1.f / (1.f + __expf(-d[3]));
            const int r = wm + mt*16 + qr;
            const int c = wn + nt*8 + qc*2;
            *reinterpret_cast<float2*>(&stg[r * GRAM_LDS + c])     = make_float2(s0, s1);
            *reinterpret_cast<float2*>(&stg[(r+8) * GRAM_LDS + c]) = make_float2(s2, s3);
        }
    }
    __syncthreads();

    // ---- direct (upper) tile write, coalesced float4 ----
    for (int v = tid; v < 128 * 32; v += 256) {
        const int r  = v >> 5;
        const int c4 = (v & 31) * 4;
        float4 t = *reinterpret_cast<const float4*>(&stg[r * GRAM_LDS + c4]);
        *reinterpret_cast<float4*>(
            &Out[(size_t)(rowBase + r) * N_NODES + colBase + c4]) = t;
    }

    // ---- mirror (lower) tile: transposed smem read, coalesced gmem rows ----
    if (bj > bi) {
        for (int v = tid; v < 128 * 32; v += 256) {
            const int cc = v & 127;         // contiguous across lanes
            const int r2 = (v >> 7) * 4;    // row quad
            float4 t = *reinterpret_cast<const float4*>(&stg[cc * GRAM_LDS + r2]);
            const size_t ob = (size_t)(colBase + r2) * N_NODES + rowBase + cc;
            Out[ob]             = t.x;
            Out[ob + N_NODES]   = t.y;
            Out[ob + 2*N_NODES] = t.z;
            Out[ob + 3*N_NODES] = t.w;
        }
    }
}

// ---------------------------------------------------------------------------
extern "C" void kernel_launch(void* const* d_in, const int* in_sizes, int n_in,
                              void* d_out, int out_size)
{
    const float* x  = (const float*)d_in[0];
    const int*   ei = (const int*)  d_in[1];
    const float* W0 = (const float*)d_in[2];
    const float* b0 = (const float*)d_in[3];
    const float* W1 = (const float*)d_in[4];
    const float* b1 = (const float*)d_in[5];
    const float* W2 = (const float*)d_in[6];
    const float* b2 = (const float*)d_in[7];
    float* out = (float*)d_out;

    void *p_h0, *p_h1, *p_z, *p_zn;
    cudaGetSymbolAddress(&p_h0, g_h0);
    cudaGetSymbolAddress(&p_h1, g_h1);
    cudaGetSymbolAddress(&p_z,  g_z);
    cudaGetSymbolAddress(&p_zn, g_zn);
    float* h0 = (float*)p_h0;
    float* h1 = (float*)p_h1;
    float* z  = (float*)p_z;
    float* zn = (float*)p_zn;

    cudaFuncSetAttribute(gram_mma_kernel,
                         cudaFuncAttributeMaxDynamicSharedMemorySize,
                         GRAM_SMEM_BYTES);

    zero_loss_kernel<<<1, 1>>>();

    // encoder
    gemm_bias_kernel<128,128,32,8,8,true><<<dim3(HID/128,   N_NODES/128), 256>>>(
        x,  W0, b0, h0, N_NODES, HID,   D_IN);
    gemm_bias_kernel<128,128,32,8,8,true><<<dim3(HID/128,   N_NODES/128), 256>>>(
        h0, W1, b1, h1, N_NODES, HID,   HID);
    gemm_bias_kernel<128, 64,32,8,4,false><<<dim3(D_OUT/64, N_NODES/128), 256>>>(
        h1, W2, b2, z,  N_NODES, D_OUT, HID);

    // normalize rows
    normalize_kernel<<<N_NODES/8, 256>>>(z, zn);

    // edge loss
    edge_loss_kernel<<<1024, 256>>>(ei, zn);

    // full similarity matrix (symmetric, tensor-core)
    gram_mma_kernel<<<dim3(N_NODES/128, N_NODES/128), 256, GRAM_SMEM_BYTES>>>(zn, out);

    // scalar loss at the end of the output buffer
    if ((long long)out_size > (long long)N_NODES * N_NODES)
        write_loss_kernel<<<1, 1>>>(out);
}

// round 5
// speedup vs baseline: 2.0384x; 1.3699x over previous
#include <cuda_runtime.h>
#include <math.h>
#include <stdint.h>

#define N_NODES 12288
#define D_IN    512
#define HID     256
#define D_OUT   64
#define E_EDGES 393216

// ---------------- scratch (device globals: no runtime allocation) ----------
__device__ float  g_h0[(size_t)N_NODES * HID];
__device__ float  g_h1[(size_t)N_NODES * HID];
__device__ float  g_zn[(size_t)N_NODES * D_OUT];
__device__ double g_loss_sum;

// ---------------------------------------------------------------------------
// tf32 helpers
// ---------------------------------------------------------------------------
__device__ __forceinline__ uint32_t f32_to_tf32(float x) {
    uint32_t r;
    asm("cvt.rna.tf32.f32 %0, %1;" : "=r"(r) : "f"(x));
    return r;
}

__device__ __forceinline__ void mma_tf32(float d[4],
                                         const uint32_t a[4],
                                         const uint32_t b[2]) {
    asm volatile(
        "mma.sync.aligned.m16n8k8.row.col.f32.tf32.tf32.f32 "
        "{%0,%1,%2,%3}, {%4,%5,%6,%7}, {%8,%9}, {%0,%1,%2,%3};"
        : "+f"(d[0]), "+f"(d[1]), "+f"(d[2]), "+f"(d[3])
        : "r"(a[0]), "r"(a[1]), "r"(a[2]), "r"(a[3]),
          "r"(b[0]), "r"(b[1]));
}

// ---------------------------------------------------------------------------
// Encoder GEMM on tensor cores:  C = act(A[M,K] @ W[K,BN_g] + bias)
//   BM = 128 rows per block, BK = 32 per k-iter.
//   BN = 128 : warps 2x4 (each 64x32)   -> layers 1,2 (relu)
//   BN = 64  : warps 4x2 (each 32x32)   -> layer 3, fused row-normalize
// A tile in smem as [row][k] (stride 36), W tile natural [k][n] (stride BN+4).
// Static smem sized to max(mainloop tiles, NORM staging tile).
// ---------------------------------------------------------------------------
#define LDA 36

template<int BN, bool RELU, bool NORM>
__global__ __launch_bounds__(256)
void gemm_mma_kernel(const float* __restrict__ A,
                     const float* __restrict__ W,
                     const float* __restrict__ bias,
                     float* __restrict__ C,
                     int K, int Nn)
{
    constexpr int LDW = BN + 4;
    constexpr int WN  = BN / 32;          // warps along n
    constexpr int WM  = 8 / WN;           // warps along m
    constexpr int MT  = 128 / (WM * 16);  // m16 tiles per warp
    constexpr int NT  = 4;                // n8 tiles per warp (32 cols)

    constexpr int NEED_MAIN = 128 * LDA + 32 * LDW;
    constexpr int NEED_STG  = NORM ? 128 * 68 : 0;
    constexpr int SMEM_FLOATS = NEED_MAIN > NEED_STG ? NEED_MAIN : NEED_STG;

    __shared__ float smem[SMEM_FLOATS];
    float* As = smem;                     // As[r*LDA + k]
    float* Ws = smem + 128 * LDA;         // Ws[k*LDW + n]

    const int tid  = threadIdx.x;
    const int lane = tid & 31;
    const int wid  = tid >> 5;
    const int wm   = (wid / WN) * (MT * 16);
    const int wn   = (wid % WN) * 32;
    const int qr   = lane >> 2;           // 0..7
    const int qc   = lane & 3;            // 0..3
    const int rowBase = blockIdx.y * 128;
    const int colBase = blockIdx.x * BN;

    float acc[MT][NT][4];
#pragma unroll
    for (int mt = 0; mt < MT; mt++)
#pragma unroll
        for (int nt = 0; nt < NT; nt++)
#pragma unroll
            for (int i = 0; i < 4; i++) acc[mt][nt][i] = 0.f;

    for (int kk = 0; kk < K; kk += 32) {
        // A tile: 128x32 floats -> tf32
#pragma unroll
        for (int v = tid; v < 128 * 8; v += 256) {
            const int r  = v >> 3;
            const int c4 = (v & 7) * 4;
            float4 t = *reinterpret_cast<const float4*>(
                &A[(size_t)(rowBase + r) * K + kk + c4]);
            uint32_t* dst = reinterpret_cast<uint32_t*>(&As[r * LDA + c4]);
            dst[0] = f32_to_tf32(t.x); dst[1] = f32_to_tf32(t.y);
            dst[2] = f32_to_tf32(t.z); dst[3] = f32_to_tf32(t.w);
        }
        // W tile: 32 x BN floats -> tf32 (natural layout)
#pragma unroll
        for (int v = tid; v < 32 * (BN/4); v += 256) {
            const int kr = v / (BN/4);
            const int n4 = (v % (BN/4)) * 4;
            float4 t = *reinterpret_cast<const float4*>(
                &W[(size_t)(kk + kr) * Nn + colBase + n4]);
            uint32_t* dst = reinterpret_cast<uint32_t*>(&Ws[kr * LDW + n4]);
            dst[0] = f32_to_tf32(t.x); dst[1] = f32_to_tf32(t.y);
            dst[2] = f32_to_tf32(t.z); dst[3] = f32_to_tf32(t.w);
        }
        __syncthreads();

#pragma unroll
        for (int k0 = 0; k0 < 32; k0 += 8) {
            uint32_t a[MT][4], b[NT][2];
#pragma unroll
            for (int mt = 0; mt < MT; mt++) {
                const uint32_t* base = reinterpret_cast<const uint32_t*>(
                    &As[(wm + mt*16 + qr) * LDA + k0 + qc]);
                a[mt][0] = base[0];
                a[mt][1] = base[8 * LDA];
                a[mt][2] = base[4];
                a[mt][3] = base[8 * LDA + 4];
            }
#pragma unroll
            for (int nt = 0; nt < NT; nt++) {
                const uint32_t* base = reinterpret_cast<const uint32_t*>(
                    &Ws[(k0 + qc) * LDW + wn + nt*8 + qr]);
                b[nt][0] = base[0];
                b[nt][1] = base[4 * LDW];
            }
#pragma unroll
            for (int mt = 0; mt < MT; mt++)
#pragma unroll
                for (int nt = 0; nt < NT; nt++)
                    mma_tf32(acc[mt][nt], a[mt], b[nt]);
        }
        __syncthreads();
    }

    if (!NORM) {
        // bias + relu, write float2 fragments directly
#pragma unroll
        for (int mt = 0; mt < MT; mt++) {
#pragma unroll
            for (int nt = 0; nt < NT; nt++) {
                float* d = acc[mt][nt];
                const int c = colBase + wn + nt*8 + qc*2;
                float bx = bias[c], by = bias[c+1];
                float2 lo = make_float2(d[0] + bx, d[1] + by);
                float2 hi = make_float2(d[2] + bx, d[3] + by);
                if (RELU) {
                    lo.x = fmaxf(lo.x, 0.f); lo.y = fmaxf(lo.y, 0.f);
                    hi.x = fmaxf(hi.x, 0.f); hi.y = fmaxf(hi.y, 0.f);
                }
                const size_t r0 = rowBase + wm + mt*16 + qr;
                *reinterpret_cast<float2*>(&C[r0 * Nn + c])     = lo;
                *reinterpret_cast<float2*>(&C[(r0+8) * Nn + c]) = hi;
            }
        }
    } else {
        // fused bias + row-normalize epilogue (BN == 64 == full row)
        constexpr int LDS = 68;
        float* stg = smem;                 // 128 x 64, stride 68
        __syncthreads();
#pragma unroll
        for (int mt = 0; mt < MT; mt++) {
#pragma unroll
            for (int nt = 0; nt < NT; nt++) {
                float* d = acc[mt][nt];
                const int c = wn + nt*8 + qc*2;
                float bx = bias[c], by = bias[c+1];
                const int r = wm + mt*16 + qr;
                *reinterpret_cast<float2*>(&stg[r * LDS + c]) =
                    make_float2(d[0] + bx, d[1] + by);
                *reinterpret_cast<float2*>(&stg[(r+8) * LDS + c]) =
                    make_float2(d[2] + bx, d[3] + by);
            }
        }
        __syncthreads();
        // each warp normalizes 16 rows
        for (int rr = 0; rr < 16; rr++) {
            const int r = wid * 16 + rr;
            float2 v = *reinterpret_cast<const float2*>(&stg[r * LDS + lane*2]);
            float ss = v.x*v.x + v.y*v.y;
#pragma unroll
            for (int o = 16; o > 0; o >>= 1)
                ss += __shfl_xor_sync(0xffffffffu, ss, o);
            float inv = rsqrtf(fmaxf(ss, 1e-30f));
            *reinterpret_cast<float2*>(&C[(size_t)(rowBase + r) * D_OUT + lane*2]) =
                make_float2(v.x * inv, v.y * inv);
        }
    }
}

// ---------------------------------------------------------------------------
// Edge reconstruction loss (edge_index is int32)
// ---------------------------------------------------------------------------
__global__ __launch_bounds__(256)
void edge_loss_kernel(const int* __restrict__ ei,
                      const float* __restrict__ Zn)
{
    const int lane = threadIdx.x & 31;
    const int warp = threadIdx.x >> 5;
    const int gw   = blockIdx.x * 8 + warp;
    const int nw   = gridDim.x * 8;
    float lsum = 0.f;
    for (int e = gw; e < E_EDGES; e += nw) {
        const int s = ei[e];
        const int d = ei[E_EDGES + e];
        float2 a = *reinterpret_cast<const float2*>(&Zn[(size_t)s * D_OUT + lane*2]);
        float2 b = *reinterpret_cast<const float2*>(&Zn[(size_t)d * D_OUT + lane*2]);
        float p = a.x*b.x + a.y*b.y;
#pragma unroll
        for (int o = 16; o > 0; o >>= 1) p += __shfl_xor_sync(0xffffffffu, p, o);
        if (lane == 0) lsum += log1pf(__expf(-p));
    }
    __shared__ float wsum[8];
    if (lane == 0) wsum[warp] = lsum;
    __syncthreads();
    if (threadIdx.x == 0) {
        float t = 0.f;
#pragma unroll
        for (int i = 0; i < 8; i++) t += wsum[i];
        atomicAdd(&g_loss_sum, (double)t);
    }
}

__global__ void zero_loss_kernel() { g_loss_sum = 0.0; }

__global__ void write_loss_kernel(float* __restrict__ out)
{
    out[(size_t)N_NODES * N_NODES] = (float)(g_loss_sum / (double)E_EDGES);
}

// ---------------------------------------------------------------------------
// Gram + sigmoid via tf32 mma: Out = sigmoid(Zn @ Zn^T), K=64.
// Upper-triangular blocks only; mirror written via smem-staged transpose.
// ---------------------------------------------------------------------------
#define GRAM_LDK  68     // smem row stride for input tiles (floats)
#define GRAM_LDS  132    // smem row stride for staging tile (floats)
#define GRAM_SMEM_BYTES (2 * 128 * GRAM_LDK * 4)   // 69,632 B (>= stage 67,584)

__global__ __launch_bounds__(256)
void gram_mma_kernel(const float* __restrict__ Z, float* __restrict__ Out)
{
    extern __shared__ float smem[];
    float* As = smem;                       // As[r*GRAM_LDK + k]
    float* Bs = smem + 128 * GRAM_LDK;

    const int bi = blockIdx.y;
    const int bj = blockIdx.x;
    if (bj < bi) return;                    // upper triangle only
    const int rowBase = bi * 128;
    const int colBase = bj * 128;

    const int tid  = threadIdx.x;
    const int lane = tid & 31;
    const int wid  = tid >> 5;
    const int wm   = (wid >> 2) * 64;
    const int wn   = (wid & 3) * 32;
    const int qr   = lane >> 2;
    const int qc   = lane & 3;

    for (int v = tid; v < 128 * 16; v += 256) {
        const int r  = v >> 4;
        const int c4 = (v & 15) * 4;
        float4 t = *reinterpret_cast<const float4*>(
            &Z[(size_t)(rowBase + r) * D_OUT + c4]);
        uint32_t* dst = reinterpret_cast<uint32_t*>(&As[r * GRAM_LDK + c4]);
        dst[0] = f32_to_tf32(t.x); dst[1] = f32_to_tf32(t.y);
        dst[2] = f32_to_tf32(t.z); dst[3] = f32_to_tf32(t.w);
    }
    if (bj != bi) {
        for (int v = tid; v < 128 * 16; v += 256) {
            const int r  = v >> 4;
            const int c4 = (v & 15) * 4;
            float4 t = *reinterpret_cast<const float4*>(
                &Z[(size_t)(colBase + r) * D_OUT + c4]);
            uint32_t* dst = reinterpret_cast<uint32_t*>(&Bs[r * GRAM_LDK + c4]);
            dst[0] = f32_to_tf32(t.x); dst[1] = f32_to_tf32(t.y);
            dst[2] = f32_to_tf32(t.z); dst[3] = f32_to_tf32(t.w);
        }
    }
    __syncthreads();

    const float* Bp = (bj == bi) ? As : Bs;

    float acc[4][4][4];
#pragma unroll
    for (int mt = 0; mt < 4; mt++)
#pragma unroll
        for (int nt = 0; nt < 4; nt++)
#pragma unroll
            for (int i = 0; i < 4; i++) acc[mt][nt][i] = 0.f;

#pragma unroll
    for (int k0 = 0; k0 < D_OUT; k0 += 8) {
        uint32_t a[4][4], b[4][2];
#pragma unroll
        for (int mt = 0; mt < 4; mt++) {
            const uint32_t* base = reinterpret_cast<const uint32_t*>(
                &As[(wm + mt*16 + qr) * GRAM_LDK + k0 + qc]);
            a[mt][0] = base[0];
            a[mt][1] = base[8 * GRAM_LDK];
            a[mt][2] = base[4];
            a[mt][3] = base[8 * GRAM_LDK + 4];
        }
#pragma unroll
        for (int nt = 0; nt < 4; nt++) {
            const uint32_t* base = reinterpret_cast<const uint32_t*>(
                &Bp[(wn + nt*8 + qr) * GRAM_LDK + k0 + qc]);
            b[nt][0] = base[0];
            b[nt][1] = base[4];
        }
#pragma unroll
        for (int mt = 0; mt < 4; mt++)
#pragma unroll
            for (int nt = 0; nt < 4; nt++)
                mma_tf32(acc[mt][nt], a[mt], b[nt]);
    }

    __syncthreads();
    float* stg = smem;                      // 128x128, stride 132
#pragma unroll
    for (int mt = 0; mt < 4; mt++) {
#pragma unroll
        for (int nt = 0; nt < 4; nt++) {
            float* d = acc[mt][nt];
            float s0 = 1.f / (1.f + __expf(-d[0]));
            float s1 = 1.f / (1.f + __expf(-d[1]));
            float s2 = 1.f / (1.f + __expf(-d[2]));
            float s3 = 1.f / (1.f + __expf(-d[3]));
            const int r = wm + mt*16 + qr;
            const int c = wn + nt*8 + qc*2;
            *reinterpret_cast<float2*>(&stg[r * GRAM_LDS + c])     = make_float2(s0, s1);
            *reinterpret_cast<float2*>(&stg[(r+8) * GRAM_LDS + c]) = make_float2(s2, s3);
        }
    }
    __syncthreads();

    for (int v = tid; v < 128 * 32; v += 256) {
        const int r  = v >> 5;
        const int c4 = (v & 31) * 4;
        float4 t = *reinterpret_cast<const float4*>(&stg[r * GRAM_LDS + c4]);
        *reinterpret_cast<float4*>(
            &Out[(size_t)(rowBase + r) * N_NODES + colBase + c4]) = t;
    }

    if (bj > bi) {
        for (int v = tid; v < 128 * 32; v += 256) {
            const int cc = v & 127;
            const int r2 = (v >> 7) * 4;
            float4 t = *reinterpret_cast<const float4*>(&stg[cc * GRAM_LDS + r2]);
            const size_t ob = (size_t)(colBase + r2) * N_NODES + rowBase + cc;
            Out[ob]             = t.x;
            Out[ob + N_NODES]   = t.y;
            Out[ob + 2*N_NODES] = t.z;
            Out[ob + 3*N_NODES] = t.w;
        }
    }
}

// ---------------------------------------------------------------------------
extern "C" void kernel_launch(void* const* d_in, const int* in_sizes, int n_in,
                              void* d_out, int out_size)
{
    const float* x  = (const float*)d_in[0];
    const int*   ei = (const int*)  d_in[1];
    const float* W0 = (const float*)d_in[2];
    const float* b0 = (const float*)d_in[3];
    const float* W1 = (const float*)d_in[4];
    const float* b1 = (const float*)d_in[5];
    const float* W2 = (const float*)d_in[6];
    const float* b2 = (const float*)d_in[7];
    float* out = (float*)d_out;

    void *p_h0, *p_h1, *p_zn;
    cudaGetSymbolAddress(&p_h0, g_h0);
    cudaGetSymbolAddress(&p_h1, g_h1);
    cudaGetSymbolAddress(&p_zn, g_zn);
    float* h0 = (float*)p_h0;
    float* h1 = (float*)p_h1;
    float* zn = (float*)p_zn;

    cudaFuncSetAttribute(gram_mma_kernel,
                         cudaFuncAttributeMaxDynamicSharedMemorySize,
                         GRAM_SMEM_BYTES);

    zero_loss_kernel<<<1, 1>>>();

    // encoder (tensor cores); layer 3 fuses bias + row-normalize -> zn
    gemm_mma_kernel<128, true,  false><<<dim3(HID/128,  N_NODES/128), 256>>>(
        x,  W0, b0, h0, D_IN, HID);
    gemm_mma_kernel<128, true,  false><<<dim3(HID/128,  N_NODES/128), 256>>>(
        h0, W1, b1, h1, HID,  HID);
    gemm_mma_kernel<64,  false, true ><<<dim3(1,        N_NODES/128), 256>>>(
        h1, W2, b2, zn, HID,  D_OUT);

    // edge loss
    edge_loss_kernel<<<1024, 256>>>(ei, zn);

    // full similarity matrix (symmetric, tensor-core)
    gram_mma_kernel<<<dim3(N_NODES/128, N_NODES/128), 256, GRAM_SMEM_BYTES>>>(zn, out);

    // scalar loss at the end of the output buffer
    if ((long long)out_size > (long long)N_NODES * N_NODES)
        write_loss_kernel<<<1, 1>>>(out);
}

// round 6
// speedup vs baseline: 2.0919x; 1.0263x over previous
#include <cuda_runtime.h>
#include <math.h>
#include <stdint.h>

#define N_NODES 12288
#define D_IN    512
#define HID     256
#define D_OUT   64
#define E_EDGES 393216

// ---------------- scratch (device globals: no runtime allocation) ----------
__device__ float  g_h0[(size_t)N_NODES * HID];
__device__ float  g_h1[(size_t)N_NODES * HID];
__device__ float  g_zn[(size_t)N_NODES * D_OUT];
__device__ double g_loss_sum;

// ---------------------------------------------------------------------------
// tf32 / cp.async helpers
// ---------------------------------------------------------------------------
__device__ __forceinline__ uint32_t f32_to_tf32(float x) {
    uint32_t r;
    asm("cvt.rna.tf32.f32 %0, %1;" : "=r"(r) : "f"(x));
    return r;
}

__device__ __forceinline__ void mma_tf32(float d[4],
                                         const uint32_t a[4],
                                         const uint32_t b[2]) {
    asm volatile(
        "mma.sync.aligned.m16n8k8.row.col.f32.tf32.tf32.f32 "
        "{%0,%1,%2,%3}, {%4,%5,%6,%7}, {%8,%9}, {%0,%1,%2,%3};"
        : "+f"(d[0]), "+f"(d[1]), "+f"(d[2]), "+f"(d[3])
        : "r"(a[0]), "r"(a[1]), "r"(a[2]), "r"(a[3]),
          "r"(b[0]), "r"(b[1]));
}

__device__ __forceinline__ void cp_async16(float* smem_dst, const float* gmem_src) {
    uint32_t s = (uint32_t)__cvta_generic_to_shared(smem_dst);
    asm volatile("cp.async.cg.shared.global [%0], [%1], 16;"
                 :: "r"(s), "l"(gmem_src));
}
#define CP_COMMIT()      asm volatile("cp.async.commit_group;")
#define CP_WAIT(n)       asm volatile("cp.async.wait_group %0;" :: "n"(n))

// ---------------------------------------------------------------------------
// Encoder GEMM on tensor cores, cp.async double-buffered:
//   C = act(A[M,K] @ W[K,*] + bias)
//   BN = 128 : warps 2x4 (each 64x32)  -> layers 1,2 (relu)
//   BN = 64  : warps 4x2 (each 32x32)  -> layer 3, fused row-normalize
// Tiles staged as raw fp32; tf32 conversion happens at fragment load.
// ---------------------------------------------------------------------------
#define LDA 36

template<int BN, bool RELU, bool NORM>
__global__ __launch_bounds__(256)
void gemm_mma_kernel(const float* __restrict__ A,
                     const float* __restrict__ W,
                     const float* __restrict__ bias,
                     float* __restrict__ C,
                     int K, int Nn)
{
    constexpr int LDW = BN + 4;
    constexpr int WN  = BN / 32;          // warps along n
    constexpr int WM  = 8 / WN;           // warps along m
    constexpr int MT  = 128 / (WM * 16);  // m16 tiles per warp
    constexpr int NT  = 4;                // n8 tiles per warp (32 cols)

    constexpr int A_FLOATS = 128 * LDA;
    constexpr int W_FLOATS = 32 * LDW;
    constexpr int NEED_MAIN = 2 * (A_FLOATS + W_FLOATS);
    constexpr int NEED_STG  = NORM ? 128 * 68 : 0;
    constexpr int SMEM_FLOATS = NEED_MAIN > NEED_STG ? NEED_MAIN : NEED_STG;

    __shared__ float smem[SMEM_FLOATS];
    // buffer layout: [As0 | Ws0 | As1 | Ws1]
    float* Asb[2] = { smem, smem + A_FLOATS + W_FLOATS };
    float* Wsb[2] = { smem + A_FLOATS, smem + 2*A_FLOATS + W_FLOATS };

    const int tid  = threadIdx.x;
    const int lane = tid & 31;
    const int wid  = tid >> 5;
    const int wm   = (wid / WN) * (MT * 16);
    const int wn   = (wid % WN) * 32;
    const int qr   = lane >> 2;           // 0..7
    const int qc   = lane & 3;            // 0..3
    const int rowBase = blockIdx.y * 128;
    const int colBase = blockIdx.x * BN;

    // per-thread fixed load slots
    auto load_tiles = [&](int kk, int buf) {
        float* As = Asb[buf];
        float* Ws = Wsb[buf];
#pragma unroll
        for (int v = tid; v < 128 * 8; v += 256) {
            const int r  = v >> 3;
            const int c4 = (v & 7) * 4;
            cp_async16(&As[r * LDA + c4],
                       &A[(size_t)(rowBase + r) * K + kk + c4]);
        }
#pragma unroll
        for (int v = tid; v < 32 * (BN/4); v += 256) {
            const int kr = v / (BN/4);
            const int n4 = (v % (BN/4)) * 4;
            cp_async16(&Ws[kr * LDW + n4],
                       &W[(size_t)(kk + kr) * Nn + colBase + n4]);
        }
        CP_COMMIT();
    };

    float acc[MT][NT][4];
#pragma unroll
    for (int mt = 0; mt < MT; mt++)
#pragma unroll
        for (int nt = 0; nt < NT; nt++)
#pragma unroll
            for (int i = 0; i < 4; i++) acc[mt][nt][i] = 0.f;

    load_tiles(0, 0);

    int buf = 0;
    for (int kk = 0; kk < K; kk += 32, buf ^= 1) {
        if (kk + 32 < K) {
            load_tiles(kk + 32, buf ^ 1);
            CP_WAIT(1);                   // current buffer complete
        } else {
            CP_WAIT(0);
        }
        __syncthreads();

        const float* As = Asb[buf];
        const float* Ws = Wsb[buf];
#pragma unroll
        for (int k0 = 0; k0 < 32; k0 += 8) {
            uint32_t a[MT][4], b[NT][2];
#pragma unroll
            for (int mt = 0; mt < MT; mt++) {
                const float* base = &As[(wm + mt*16 + qr) * LDA + k0 + qc];
                a[mt][0] = f32_to_tf32(base[0]);
                a[mt][1] = f32_to_tf32(base[8 * LDA]);
                a[mt][2] = f32_to_tf32(base[4]);
                a[mt][3] = f32_to_tf32(base[8 * LDA + 4]);
            }
#pragma unroll
            for (int nt = 0; nt < NT; nt++) {
                const float* base = &Ws[(k0 + qc) * LDW + wn + nt*8 + qr];
                b[nt][0] = f32_to_tf32(base[0]);
                b[nt][1] = f32_to_tf32(base[4 * LDW]);
            }
#pragma unroll
            for (int mt = 0; mt < MT; mt++)
#pragma unroll
                for (int nt = 0; nt < NT; nt++)
                    mma_tf32(acc[mt][nt], a[mt], b[nt]);
        }
        __syncthreads();                  // safe to overwrite this buffer later
    }

    if (!NORM) {
        // bias + relu, write float2 fragments directly
#pragma unroll
        for (int mt = 0; mt < MT; mt++) {
#pragma unroll
            for (int nt = 0; nt < NT; nt++) {
                float* d = acc[mt][nt];
                const int c = colBase + wn + nt*8 + qc*2;
                float bx = bias[c], by = bias[c+1];
                float2 lo = make_float2(d[0] + bx, d[1] + by);
                float2 hi = make_float2(d[2] + bx, d[3] + by);
                if (RELU) {
                    lo.x = fmaxf(lo.x, 0.f); lo.y = fmaxf(lo.y, 0.f);
                    hi.x = fmaxf(hi.x, 0.f); hi.y = fmaxf(hi.y, 0.f);
                }
                const size_t r0 = rowBase + wm + mt*16 + qr;
                *reinterpret_cast<float2*>(&C[r0 * Nn + c])     = lo;
                *reinterpret_cast<float2*>(&C[(r0+8) * Nn + c]) = hi;
            }
        }
    } else {
        // fused bias + row-normalize epilogue (BN == 64 == full row)
        constexpr int LDS = 68;
        float* stg = smem;                // 128 x 64, stride 68
        __syncthreads();
#pragma unroll
        for (int mt = 0; mt < MT; mt++) {
#pragma unroll
            for (int nt = 0; nt < NT; nt++) {
                float* d = acc[mt][nt];
                const int c = wn + nt*8 + qc*2;
                float bx = bias[c], by = bias[c+1];
                const int r = wm + mt*16 + qr;
                *reinterpret_cast<float2*>(&stg[r * LDS + c]) =
                    make_float2(d[0] + bx, d[1] + by);
                *reinterpret_cast<float2*>(&stg[(r+8) * LDS + c]) =
                    make_float2(d[2] + bx, d[3] + by);
            }
        }
        __syncthreads();
        for (int rr = 0; rr < 16; rr++) {
            const int r = wid * 16 + rr;
            float2 v = *reinterpret_cast<const float2*>(&stg[r * LDS + lane*2]);
            float ss = v.x*v.x + v.y*v.y;
#pragma unroll
            for (int o = 16; o > 0; o >>= 1)
                ss += __shfl_xor_sync(0xffffffffu, ss, o);
            float inv = rsqrtf(fmaxf(ss, 1e-30f));
            *reinterpret_cast<float2*>(&C[(size_t)(rowBase + r) * D_OUT + lane*2]) =
                make_float2(v.x * inv, v.y * inv);
        }
    }
}

// ---------------------------------------------------------------------------
// Edge reconstruction loss (edge_index is int32)
// ---------------------------------------------------------------------------
__global__ __launch_bounds__(256)
void edge_loss_kernel(const int* __restrict__ ei,
                      const float* __restrict__ Zn)
{
    const int lane = threadIdx.x & 31;
    const int warp = threadIdx.x >> 5;
    const int gw   = blockIdx.x * 8 + warp;
    const int nw   = gridDim.x * 8;
    float lsum = 0.f;
    for (int e = gw; e < E_EDGES; e += nw) {
        const int s = ei[e];
        const int d = ei[E_EDGES + e];
        float2 a = *reinterpret_cast<const float2*>(&Zn[(size_t)s * D_OUT + lane*2]);
        float2 b = *reinterpret_cast<const float2*>(&Zn[(size_t)d * D_OUT + lane*2]);
        float p = a.x*b.x + a.y*b.y;
#pragma unroll
        for (int o = 16; o > 0; o >>= 1) p += __shfl_xor_sync(0xffffffffu, p, o);
        if (lane == 0) lsum += log1pf(__expf(-p));
    }
    __shared__ float wsum[8];
    if (lane == 0) wsum[warp] = lsum;
    __syncthreads();
    if (threadIdx.x == 0) {
        float t = 0.f;
#pragma unroll
        for (int i = 0; i < 8; i++) t += wsum[i];
        atomicAdd(&g_loss_sum, (double)t);
    }
}

__global__ void zero_loss_kernel() { g_loss_sum = 0.0; }

__global__ void write_loss_kernel(float* __restrict__ out)
{
    out[(size_t)N_NODES * N_NODES] = (float)(g_loss_sum / (double)E_EDGES);
}

// ---------------------------------------------------------------------------
// Gram + sigmoid via tf32 mma: Out = sigmoid(Zn @ Zn^T), K=64.
// Upper-triangular blocks; direct tile written straight from registers
// (float2 fragments cover full 32B sectors); mirror tile staged + transposed.
// ---------------------------------------------------------------------------
#define GRAM_LDK  68
#define GRAM_LDS  132
#define GRAM_SMEM_BYTES (2 * 128 * GRAM_LDK * 4)   // 69,632 B (>= stage 67,584)

__global__ __launch_bounds__(256)
void gram_mma_kernel(const float* __restrict__ Z, float* __restrict__ Out)
{
    extern __shared__ float smem[];
    float* As = smem;
    float* Bs = smem + 128 * GRAM_LDK;

    const int bi = blockIdx.y;
    const int bj = blockIdx.x;
    if (bj < bi) return;
    const int rowBase = bi * 128;
    const int colBase = bj * 128;

    const int tid  = threadIdx.x;
    const int lane = tid & 31;
    const int wid  = tid >> 5;
    const int wm   = (wid >> 2) * 64;
    const int wn   = (wid & 3) * 32;
    const int qr   = lane >> 2;
    const int qc   = lane & 3;

    for (int v = tid; v < 128 * 16; v += 256) {
        const int r  = v >> 4;
        const int c4 = (v & 15) * 4;
        float4 t = *reinterpret_cast<const float4*>(
            &Z[(size_t)(rowBase + r) * D_OUT + c4]);
        uint32_t* dst = reinterpret_cast<uint32_t*>(&As[r * GRAM_LDK + c4]);
        dst[0] = f32_to_tf32(t.x); dst[1] = f32_to_tf32(t.y);
        dst[2] = f32_to_tf32(t.z); dst[3] = f32_to_tf32(t.w);
    }
    if (bj != bi) {
        for (int v = tid; v < 128 * 16; v += 256) {
            const int r  = v >> 4;
            const int c4 = (v & 15) * 4;
            float4 t = *reinterpret_cast<const float4*>(
                &Z[(size_t)(colBase + r) * D_OUT + c4]);
            uint32_t* dst = reinterpret_cast<uint32_t*>(&Bs[r * GRAM_LDK + c4]);
            dst[0] = f32_to_tf32(t.x); dst[1] = f32_to_tf32(t.y);
            dst[2] = f32_to_tf32(t.z); dst[3] = f32_to_tf32(t.w);
        }
    }
    __syncthreads();

    const float* Bp = (bj == bi) ? As : Bs;

    float acc[4][4][4];
#pragma unroll
    for (int mt = 0; mt < 4; mt++)
#pragma unroll
        for (int nt = 0; nt < 4; nt++)
#pragma unroll
            for (int i = 0; i < 4; i++) acc[mt][nt][i] = 0.f;

#pragma unroll
    for (int k0 = 0; k0 < D_OUT; k0 += 8) {
        uint32_t a[4][4], b[4][2];
#pragma unroll
        for (int mt = 0; mt < 4; mt++) {
            const uint32_t* base = reinterpret_cast<const uint32_t*>(
                &As[(wm + mt*16 + qr) * GRAM_LDK + k0 + qc]);
            a[mt][0] = base[0];
            a[mt][1] = base[8 * GRAM_LDK];
            a[mt][2] = base[4];
            a[mt][3] = base[8 * GRAM_LDK + 4];
        }
#pragma unroll
        for (int nt = 0; nt < 4; nt++) {
            const uint32_t* base = reinterpret_cast<const uint32_t*>(
                &Bp[(wn + nt*8 + qr) * GRAM_LDK + k0 + qc]);
            b[nt][0] = base[0];
            b[nt][1] = base[4];
        }
#pragma unroll
        for (int mt = 0; mt < 4; mt++)
#pragma unroll
            for (int nt = 0; nt < 4; nt++)
                mma_tf32(acc[mt][nt], a[mt], b[nt]);
    }

    // sigmoid in registers, write direct (upper) tile straight from regs
#pragma unroll
    for (int mt = 0; mt < 4; mt++) {
#pragma unroll
        for (int nt = 0; nt < 4; nt++) {
            float* d = acc[mt][nt];
            d[0] = 1.f / (1.f + __expf(-d[0]));
            d[1] = 1.f / (1.f + __expf(-d[1]));
            d[2] = 1.f / (1.f + __expf(-d[2]));
            d[3] = 1.f / (1.f + __expf(-d[3]));
            const size_t r = rowBase + wm + mt*16 + qr;
            const int    c = colBase + wn + nt*8 + qc*2;
            *reinterpret_cast<float2*>(&Out[r * N_NODES + c]) =
                make_float2(d[0], d[1]);
            *reinterpret_cast<float2*>(&Out[(r+8) * N_NODES + c]) =
                make_float2(d[2], d[3]);
        }
    }

    // mirror (lower) tile: stage + transposed write (off-diagonal only)
    if (bj > bi) {
        __syncthreads();
        float* stg = smem;                  // 128x128, stride 132
#pragma unroll
        for (int mt = 0; mt < 4; mt++) {
#pragma unroll
            for (int nt = 0; nt < 4; nt++) {
                float* d = acc[mt][nt];
                const int r = wm + mt*16 + qr;
                const int c = wn + nt*8 + qc*2;
                *reinterpret_cast<float2*>(&stg[r * GRAM_LDS + c]) =
                    make_float2(d[0], d[1]);
                *reinterpret_cast<float2*>(&stg[(r+8) * GRAM_LDS + c]) =
                    make_float2(d[2], d[3]);
            }
        }
        __syncthreads();
        for (int v = tid; v < 128 * 32; v += 256) {
            const int cc = v & 127;
            const int r2 = (v >> 7) * 4;
            float4 t = *reinterpret_cast<const float4*>(&stg[cc * GRAM_LDS + r2]);
            const size_t ob = (size_t)(colBase + r2) * N_NODES + rowBase + cc;
            Out[ob]             = t.x;
            Out[ob + N_NODES]   = t.y;
            Out[ob + 2*N_NODES] = t.z;
            Out[ob + 3*N_NODES] = t.w;
        }
    }
}

// ---------------------------------------------------------------------------
extern "C" void kernel_launch(void* const* d_in, const int* in_sizes, int n_in,
                              void* d_out, int out_size)
{
    const float* x  = (const float*)d_in[0];
    const int*   ei = (const int*)  d_in[1];
    const float* W0 = (const float*)d_in[2];
    const float* b0 = (const float*)d_in[3];
    const float* W1 = (const float*)d_in[4];
    const float* b1 = (const float*)d_in[5];
    const float* W2 = (const float*)d_in[6];
    const float* b2 = (const float*)d_in[7];
    float* out = (float*)d_out;

    void *p_h0, *p_h1, *p_zn;
    cudaGetSymbolAddress(&p_h0, g_h0);
    cudaGetSymbolAddress(&p_h1, g_h1);
    cudaGetSymbolAddress(&p_zn, g_zn);
    float* h0 = (float*)p_h0;
    float* h1 = (float*)p_h1;
    float* zn = (float*)p_zn;

    cudaFuncSetAttribute(gram_mma_kernel,
                         cudaFuncAttributeMaxDynamicSharedMemorySize,
                         GRAM_SMEM_BYTES);

    zero_loss_kernel<<<1, 1>>>();

    // encoder (tensor cores, cp.async double-buffered)
    gemm_mma_kernel<128, true,  false><<<dim3(HID/128,  N_NODES/128), 256>>>(
        x,  W0, b0, h0, D_IN, HID);
    gemm_mma_kernel<128, true,  false><<<dim3(HID/128,  N_NODES/128), 256>>>(
        h0, W1, b1, h1, HID,  HID);
    gemm_mma_kernel<64,  false, true ><<<dim3(1,        N_NODES/128), 256>>>(
        h1, W2, b2, zn, HID,  D_OUT);

    // edge loss
    edge_loss_kernel<<<1024, 256>>>(ei, zn);

    // full similarity matrix (symmetric, tensor-core)
    gram_mma_kernel<<<dim3(N_NODES/128, N_NODES/128), 256, GRAM_SMEM_BYTES>>>(zn, out);

    // scalar loss at the end of the output buffer
    if ((long long)out_size > (long long)N_NODES * N_NODES)
        write_loss_kernel<<<1, 1>>>(out);
}